// round 14
// baseline (speedup 1.0000x reference)
#include <cuda_runtime.h>
#include <cuda_fp16.h>
#include <cstdint>
#include <math.h>

// Shapes (fixed)
constexpr int NROW = 128;
constexpr int DDIM = 512;
constexpr int CDIM = 8192;
constexpr int NQ   = 32768;

// ---------------- device scratch ----------------
__device__ __align__(16) float g_s1[(size_t)NROW * NQ];
__device__ __align__(16) float g_s2[(size_t)NROW * NQ];
__device__ __align__(16) unsigned short g_a1[NROW * DDIM]; // fp16 normalized new_embeds
__device__ __align__(16) unsigned short g_a2[NROW * CDIM]; // fp16 new_logits
__device__ int   g_qlab[NQ];
__device__ float g_part[256 * 8];     // per (row, half): m1,l1,m2,l2,sw,s1w,s2w,cnt

// ---------------- small helpers ----------------
__device__ __forceinline__ uint32_t smem_u32(const void* p) {
    uint32_t a;
    asm("{ .reg .u64 t; cvta.to.shared.u64 t, %1; cvt.u32.u64 %0, t; }" : "=r"(a) : "l"(p));
    return a;
}
__device__ __forceinline__ void ldm4(uint32_t* r, uint32_t addr) {
    asm volatile("ldmatrix.sync.aligned.m8n8.x4.shared.b16 {%0,%1,%2,%3}, [%4];"
                 : "=r"(r[0]), "=r"(r[1]), "=r"(r[2]), "=r"(r[3]) : "r"(addr));
}
__device__ __forceinline__ void mma_f16(float* d, const uint32_t* a, const uint32_t* b) {
    asm volatile(
        "mma.sync.aligned.m16n8k16.row.col.f32.f16.f16.f32 "
        "{%0,%1,%2,%3}, {%4,%5,%6,%7}, {%8,%9}, {%0,%1,%2,%3};"
        : "+f"(d[0]), "+f"(d[1]), "+f"(d[2]), "+f"(d[3])
        : "r"(a[0]), "r"(a[1]), "r"(a[2]), "r"(a[3]), "r"(b[0]), "r"(b[1]));
}
#define CP16(saddr, gptr) \
    asm volatile("cp.async.cg.shared.global [%0], [%1], 16;" :: "r"(saddr), "l"(gptr))
#define CP_COMMIT() asm volatile("cp.async.commit_group;" ::: "memory")
#define CP_WAIT0()  asm volatile("cp.async.wait_group 0;" ::: "memory")

// ---------------- fused prepass: half_logits + normalize + qlab ----------------
__global__ __launch_bounds__(256) void prepass(
    const float* __restrict__ new_logits, const float* __restrict__ new_embeds,
    const int* __restrict__ ql, const int* __restrict__ labels,
    const int* __restrict__ hdrp)
{
    const int b = blockIdx.x, tid = threadIdx.x;
    if (b < 1024) {
        // new_logits -> fp16 (128*8192 floats, 1 float4/thread)
        int idx = (b * 256 + tid) * 4;
        float4 v = *(const float4*)(new_logits + idx);
        __half2 h0 = __floats2half2_rn(v.x, v.y);
        __half2 h1 = __floats2half2_rn(v.z, v.w);
        uint2 p; p.x = *(uint32_t*)&h0; p.y = *(uint32_t*)&h1;
        *(uint2*)(g_a2 + idx) = p;
    } else if (b < 1152) {
        // normalize new_embeds row (b-1024) -> fp16
        int i = b - 1024;
        const float* xr = new_embeds + (size_t)i * DDIM;
        float s = 0.f;
        for (int d = tid; d < DDIM; d += 256) { float v = xr[d]; s += v * v; }
        for (int o = 16; o; o >>= 1) s += __shfl_down_sync(0xffffffffu, s, o);
        __shared__ float sh[8];
        if ((tid & 31) == 0) sh[tid >> 5] = s;
        __syncthreads();
        __shared__ float invs;
        if (tid == 0) {
            float tot = 0.f;
            for (int w = 0; w < 8; w++) tot += sh[w];
            invs = 1.0f / fmaxf(sqrtf(tot), 1e-12f);
        }
        __syncthreads();
        float iv = invs;
        for (int d = tid; d < DDIM; d += 256)
            g_a1[i * DDIM + d] = __half_as_ushort(__float2half_rn(xr[d] * iv));
    } else {
        // queue labels (128 blocks x 256 = 32768)
        int j = (b - 1152) * 256 + tid;
        int hdr = *hdrp;
        int r = (j - hdr) & (NQ - 1);
        g_qlab[j] = (r < NROW) ? labels[r] : ql[j];
    }
}

// ---------------- fused fp16 GEMMs: row-per-thread copy/convert (conflict-free) ----
// blocks [0,256):   l2 (K=CDIM) -> g_s2
// blocks [256,512): l1 (K=DDIM) -> g_s1
// CTA tile 128x128, BK=32; 8 warps (4M x 2N), warp tile 32x64.
// threads 0-127: B row owners (cp.async fp32 staging + convert->fp16 tile)
// threads 128-255: A row owners (cp.async fp16 direct)
constexpr int BPAD = 80;                 // fp16 tile row stride (conflict-free ldmatrix)
constexpr int FSTR = 144;                // fp32 staging row stride
constexpr int SZ_T = 128 * BPAD;         // 10240
constexpr int SZ_F = 128 * FSTR;         // 18432
constexpr int O_A   = 0;                 // [2 stages x 10240]
constexpr int O_B16 = 2 * SZ_T;          // 20480 [2 stages x 10240]
constexpr int O_FS  = 4 * SZ_T;          // 40960 [2 stages x 18432]
constexpr int GEMM_SMEM = O_FS + 2 * SZ_F;   // 77824 -> 2 CTAs/SM

__global__ __launch_bounds__(256, 2) void gemm_mma(
    const float* __restrict__ Bq2, const float* __restrict__ Bold2,
    const float* __restrict__ Bq1, const float* __restrict__ Bold1,
    const int* __restrict__ hdrp)
{
    extern __shared__ char smem[];
    const uint32_t sb = smem_u32(smem);
    const int tid = threadIdx.x, lane = tid & 31, wid = tid >> 5;
    const int wm = wid >> 1, wn = wid & 1;
    const int bidx = blockIdx.x;

    // select problem (l2 long blocks first)
    const bool is2 = (bidx < 256);
    const int n0 = (is2 ? bidx : bidx - 256) * 128;
    const int K  = is2 ? CDIM : DDIM;
    const unsigned short* A = is2 ? g_a2 : g_a1;
    const float* Bq   = is2 ? Bq2 : Bq1;
    const float* Bold = is2 ? Bold2 : Bold1;
    float* out = is2 ? g_s2 : g_s1;
    const int nch = K >> 5;

    // role assignment
    const bool isB = (tid < 128);
    const int prow = isB ? tid : (tid - 128);       // owned row (B or A)
    const int hdr = *hdrp;

    // B: one thread per queue row (circular redirect)
    const int jq = n0 + prow;
    const int rr = (jq - hdr) & (NQ - 1);
    const char* gB = (const char*)((rr < NROW) ? (Bold + (size_t)rr * K)
                                               : (Bq + (size_t)jq * K));
    const uint32_t sBrow = sb + O_FS + prow * FSTR;     // staging row base (+stage)

    // A: one thread per A row
    const char* gA = (const char*)A + (size_t)prow * K * 2;
    const uint32_t sArow = sb + O_A + prow * BPAD;      // tile row base (+stage)

    // ldmatrix lane addressing
    const int g = lane >> 3, lr = lane & 7;
    const uint32_t aRowOff = (uint32_t)(wm * 32 + (g & 1) * 8 + lr) * BPAD + (g >> 1) * 16;
    const uint32_t bRowOff = (uint32_t)(wn * 64 + (g >> 1) * 8 + lr) * BPAD + (g & 1) * 16;

    float acc[2][8][4];
#pragma unroll
    for (int mt = 0; mt < 2; mt++)
#pragma unroll
        for (int nt = 0; nt < 8; nt++)
#pragma unroll
            for (int u = 0; u < 4; u++) acc[mt][nt][u] = 0.f;

    auto cpA = [&](int c, int st) {                 // threads 128-255: 64B of fp16
        const char* s0 = gA + (size_t)c * 64;
        uint32_t d0 = sArow + st * SZ_T;
#pragma unroll
        for (int i = 0; i < 4; i++) CP16(d0 + 16 * i, s0 + 16 * i);
    };
    auto cpB = [&](int c, int st) {                 // threads 0-127: 128B of fp32
        const char* s0 = gB + (size_t)c * 128;
        uint32_t d0 = sBrow + st * SZ_F;
#pragma unroll
        for (int i = 0; i < 8; i++) CP16(d0 + 16 * i, s0 + 16 * i);
    };
    // convert own row staged in fp32 stage st2 -> fp16 tile stage st2 (two 16-float passes)
    auto convertB = [&](int st2) {
        const char* src = smem + O_FS + st2 * SZ_F + prow * FSTR;
        char* dst = smem + O_B16 + st2 * SZ_T + prow * BPAD;
#pragma unroll
        for (int h = 0; h < 2; h++) {
            float4 f0 = *(const float4*)(src + h * 64);
            float4 f1 = *(const float4*)(src + h * 64 + 16);
            float4 f2 = *(const float4*)(src + h * 64 + 32);
            float4 f3 = *(const float4*)(src + h * 64 + 48);
            __half2 h0 = __floats2half2_rn(f0.x, f0.y);
            __half2 h1 = __floats2half2_rn(f0.z, f0.w);
            __half2 h2 = __floats2half2_rn(f1.x, f1.y);
            __half2 h3 = __floats2half2_rn(f1.z, f1.w);
            __half2 h4 = __floats2half2_rn(f2.x, f2.y);
            __half2 h5 = __floats2half2_rn(f2.z, f2.w);
            __half2 h6 = __floats2half2_rn(f3.x, f3.y);
            __half2 h7 = __floats2half2_rn(f3.z, f3.w);
            uint4 p0, p1;
            p0.x = *(uint32_t*)&h0; p0.y = *(uint32_t*)&h1;
            p0.z = *(uint32_t*)&h2; p0.w = *(uint32_t*)&h3;
            p1.x = *(uint32_t*)&h4; p1.y = *(uint32_t*)&h5;
            p1.z = *(uint32_t*)&h6; p1.w = *(uint32_t*)&h7;
            *(uint4*)(dst + h * 32) = p0;
            *(uint4*)(dst + h * 32 + 16) = p1;
        }
    };
    // compute chunk c; converters (tid<128) convert next chunk between ks0 and ks1
    auto computeConv = [&](int c, bool conv) {
        const int st = c & 1;
        const uint32_t bA = sb + O_A + st * SZ_T + aRowOff;
        const uint32_t bB = sb + O_B16 + st * SZ_T + bRowOff;
        {   // ks = 0
            uint32_t a[2][4], b[4][4];
            ldm4(a[0], bA);
            ldm4(a[1], bA + 16 * BPAD);
#pragma unroll
            for (int p = 0; p < 4; p++) ldm4(b[p], bB + p * 16 * BPAD);
#pragma unroll
            for (int mt = 0; mt < 2; mt++)
#pragma unroll
                for (int nt = 0; nt < 8; nt++)
                    mma_f16(acc[mt][nt], a[mt], &b[nt >> 1][(nt & 1) * 2]);
        }
        if (conv && isB) convertB(st ^ 1);   // hidden under ks0 MMA drain
        {   // ks = 1
            uint32_t a[2][4], b[4][4];
            ldm4(a[0], bA + 32);
            ldm4(a[1], bA + 16 * BPAD + 32);
#pragma unroll
            for (int p = 0; p < 4; p++) ldm4(b[p], bB + p * 16 * BPAD + 32);
#pragma unroll
            for (int mt = 0; mt < 2; mt++)
#pragma unroll
                for (int nt = 0; nt < 8; nt++)
                    mma_f16(acc[mt][nt], a[mt], &b[nt >> 1][(nt & 1) * 2]);
        }
    };

    // ---- prologue: land B(0), B(1), A(0); convert B(0) ----
    if (isB) { cpB(0, 0); cpB(1, 1); }
    else     { cpA(0, 0); }
    CP_COMMIT();
    CP_WAIT0();
    __syncthreads();
    if (isB) convertB(0);
    __syncthreads();

    // ---- main loop: one wait + one barrier per chunk ----
    for (int c = 0; c < nch; c++) {
        const int st = c & 1;
        if (c > 0) { CP_WAIT0(); __syncthreads(); }
        if (isB) { if (c + 2 < nch) cpB(c + 2, st); }
        else     { if (c + 1 < nch) cpA(c + 1, st ^ 1); }
        CP_COMMIT();
        computeConv(c, c + 1 < nch);
    }

    // ---- epilogue ----
    const int qr = lane >> 2, qc = (lane & 3) * 2;
#pragma unroll
    for (int mt = 0; mt < 2; mt++) {
        const int row = wm * 32 + mt * 16 + qr;
#pragma unroll
        for (int nt = 0; nt < 8; nt++) {
            const int col = n0 + wn * 64 + nt * 8 + qc;
            float2 v0; v0.x = acc[mt][nt][0]; v0.y = acc[mt][nt][1];
            float2 v1; v1.x = acc[mt][nt][2]; v1.y = acc[mt][nt][3];
            *(float2*)(out + (size_t)row * NQ + col) = v0;
            *(float2*)(out + (size_t)(row + 8) * NQ + col) = v1;
        }
    }
}

// ---------------- per-row reduction: 2 blocks per row (half-Q each) ----------------
__global__ __launch_bounds__(256) void row_reduce(
    const float* __restrict__ old_embeds, const float* __restrict__ feat_queue,
    const int* __restrict__ labels, const int* __restrict__ hdrp)
{
    const int i = blockIdx.x >> 1, half = blockIdx.x & 1, tid = threadIdx.x;
    const int lbl = labels[i];
    const int hdr = *hdrp;
    const int j0 = half * (NQ / 2);
    const float4* s1r = (const float4*)(g_s1 + (size_t)i * NQ + j0);
    const float4* s2r = (const float4*)(g_s2 + (size_t)i * NQ + j0);
    const int4*   ql4 = (const int4*)(g_qlab + j0);
    const float* oei = old_embeds + (size_t)i * DDIM;
    constexpr int NV = (NQ / 2) / 4;

    float m1 = -INFINITY, m2 = -INFINITY;
    for (int v = tid; v < NV; v += 256) {
        float4 a = s1r[v], b = s2r[v];
        m1 = fmaxf(fmaxf(fmaxf(m1, a.x), fmaxf(a.y, a.z)), a.w);
        m2 = fmaxf(fmaxf(fmaxf(m2, b.x), fmaxf(b.y, b.z)), b.w);
    }
    for (int o = 16; o; o >>= 1) {
        m1 = fmaxf(m1, __shfl_xor_sync(0xffffffffu, m1, o));
        m2 = fmaxf(m2, __shfl_xor_sync(0xffffffffu, m2, o));
    }
    __shared__ float shm1[8], shm2[8];
    if ((tid & 31) == 0) { shm1[tid >> 5] = m1; shm2[tid >> 5] = m2; }
    __syncthreads();
    float M1 = shm1[0], M2 = shm2[0];
    for (int w = 1; w < 8; w++) { M1 = fmaxf(M1, shm1[w]); M2 = fmaxf(M2, shm2[w]); }

    float l1 = 0.f, l2 = 0.f, sw = 0.f, s1w = 0.f, s2w = 0.f, cnt = 0.f;
    for (int v = tid; v < NV; v += 256) {
        float4 a = s1r[v], b = s2r[v];
        l1 += __expf(a.x - M1) + __expf(a.y - M1) + __expf(a.z - M1) + __expf(a.w - M1);
        l2 += __expf(b.x - M2) + __expf(b.y - M2) + __expf(b.z - M2) + __expf(b.w - M2);
        int4 q = ql4[v];
        if (q.x == lbl || q.y == lbl || q.z == lbl || q.w == lbl) {
            const float va[4] = {a.x, a.y, a.z, a.w};
            const float vb[4] = {b.x, b.y, b.z, b.w};
            const int   qq[4] = {q.x, q.y, q.z, q.w};
#pragma unroll
            for (int e = 0; e < 4; e++) {
                if (qq[e] != lbl) continue;
                int jj = j0 + v * 4 + e;
                int r = (jj - hdr) & (NQ - 1);
                const float* frow = (r < NROW) ? (old_embeds + (size_t)r * DDIM)
                                               : (feat_queue + (size_t)jj * DDIM);
                float dot = 0.f;
#pragma unroll 8
                for (int d = 0; d < DDIM; d++) dot = fmaf(oei[d], frow[d], dot);
                float w = 0.5f * (dot + 1.0f);
                sw += w; s1w += w * va[e]; s2w += w * vb[e]; cnt += 1.f;
            }
        }
    }
    for (int o = 16; o; o >>= 1) {
        l1  += __shfl_down_sync(0xffffffffu, l1, o);
        l2  += __shfl_down_sync(0xffffffffu, l2, o);
        sw  += __shfl_down_sync(0xffffffffu, sw, o);
        s1w += __shfl_down_sync(0xffffffffu, s1w, o);
        s2w += __shfl_down_sync(0xffffffffu, s2w, o);
        cnt += __shfl_down_sync(0xffffffffu, cnt, o);
    }
    __shared__ float shl1[8], shl2[8], shsw[8], shs1[8], shs2[8], shc[8];
    if ((tid & 31) == 0) {
        int w = tid >> 5;
        shl1[w] = l1; shl2[w] = l2; shsw[w] = sw; shs1[w] = s1w; shs2[w] = s2w; shc[w] = cnt;
    }
    __syncthreads();
    if (tid == 0) {
        float L1 = 0, L2 = 0, SW = 0, S1 = 0, S2 = 0, CN = 0;
        for (int w = 0; w < 8; w++) {
            L1 += shl1[w]; L2 += shl2[w]; SW += shsw[w];
            S1 += shs1[w]; S2 += shs2[w]; CN += shc[w];
        }
        float* p = g_part + blockIdx.x * 8;
        p[0] = M1; p[1] = L1; p[2] = M2; p[3] = L2;
        p[4] = SW; p[5] = S1; p[6] = S2; p[7] = CN;
    }
}

// ---------------- finalize ----------------
__global__ void finalize(float* __restrict__ out) {
    int tid = threadIdx.x;   // 128 threads, one row each
    const float* pa = g_part + (2 * tid) * 8;
    const float* pb = g_part + (2 * tid + 1) * 8;
    float M1 = fmaxf(pa[0], pb[0]);
    float L1 = pa[1] * __expf(pa[0] - M1) + pb[1] * __expf(pb[0] - M1);
    float M2 = fmaxf(pa[2], pb[2]);
    float L2 = pa[3] * __expf(pa[2] - M2) + pb[3] * __expf(pb[2] - M2);
    float SW = pa[4] + pb[4];
    float S1 = pa[5] + pb[5];
    float S2 = pa[6] + pb[6];
    float CN = pa[7] + pb[7];
    float lse1 = M1 + logf(L1);
    float lse2 = M2 + logf(L2);
    float ic = 1.0f / CN;
    float t1 = (S1 - lse1 * SW) * ic;
    float t2 = (S2 - lse2 * SW) * ic;
    for (int o = 16; o; o >>= 1) {
        t1 += __shfl_down_sync(0xffffffffu, t1, o);
        t2 += __shfl_down_sync(0xffffffffu, t2, o);
    }
    __shared__ float sh1[4], sh2[4];
    if ((tid & 31) == 0) { sh1[tid >> 5] = t1; sh2[tid >> 5] = t2; }
    __syncthreads();
    if (tid == 0) {
        out[0] = -(sh1[0] + sh1[1] + sh1[2] + sh1[3]) / (float)NROW;
        out[1] = -(sh2[0] + sh2[1] + sh2[2] + sh2[3]) / (float)NROW;
    }
}

// ---------------- launch ----------------
extern "C" void kernel_launch(void* const* d_in, const int* in_sizes, int n_in,
                              void* d_out, int out_size) {
    const float* old_embeds   = (const float*)d_in[0];
    const float* old_logits   = (const float*)d_in[1];
    const float* new_embeds   = (const float*)d_in[2];
    const float* new_logits   = (const float*)d_in[3];
    const int*   labels       = (const int*)d_in[4];
    const float* feat_queue   = (const float*)d_in[5];
    const float* logit_queue  = (const float*)d_in[6];
    const int*   queue_labels = (const int*)d_in[7];
    const int*   header       = (const int*)d_in[8];
    float* out = (float*)d_out;

    cudaFuncSetAttribute(gemm_mma, cudaFuncAttributeMaxDynamicSharedMemorySize, GEMM_SMEM);

    prepass<<<1280, 256>>>(new_logits, new_embeds, queue_labels, labels, header);

    // fused: [0,256) l2 (K=CDIM), [256,512) l1 (K=DDIM)
    gemm_mma<<<512, 256, GEMM_SMEM>>>(logit_queue, old_logits,
                                      feat_queue, old_embeds, header);

    row_reduce<<<2 * NROW, 256>>>(old_embeds, feat_queue, labels, header);
    finalize<<<1, 128>>>(out);
}

// round 15
// speedup vs baseline: 1.1392x; 1.1392x over previous
#include <cuda_runtime.h>
#include <cuda_fp16.h>
#include <cstdint>
#include <math.h>

// Shapes (fixed)
constexpr int NROW = 128;
constexpr int DDIM = 512;
constexpr int CDIM = 8192;
constexpr int NQ   = 32768;

// ---------------- device scratch ----------------
__device__ __align__(16) unsigned short g_a1[NROW * DDIM]; // fp16 normalized new_embeds
__device__ __align__(16) unsigned short g_a2[NROW * CDIM]; // fp16 new_logits
__device__ int   g_qlab[NQ];
// per (problem, ctaN, row): m, l, sw, s1w, cnt, pad[3]
__device__ __align__(16) float g_pp[2][256][NROW][8];
__device__ float g_terms[2 * NROW];

// ---------------- small helpers ----------------
__device__ __forceinline__ uint32_t smem_u32(const void* p) {
    uint32_t a;
    asm("{ .reg .u64 t; cvta.to.shared.u64 t, %1; cvt.u32.u64 %0, t; }" : "=r"(a) : "l"(p));
    return a;
}
__device__ __forceinline__ void ldm4(uint32_t* r, uint32_t addr) {
    asm volatile("ldmatrix.sync.aligned.m8n8.x4.shared.b16 {%0,%1,%2,%3}, [%4];"
                 : "=r"(r[0]), "=r"(r[1]), "=r"(r[2]), "=r"(r[3]) : "r"(addr));
}
__device__ __forceinline__ void mma_f16(float* d, const uint32_t* a, const uint32_t* b) {
    asm volatile(
        "mma.sync.aligned.m16n8k16.row.col.f32.f16.f16.f32 "
        "{%0,%1,%2,%3}, {%4,%5,%6,%7}, {%8,%9}, {%0,%1,%2,%3};"
        : "+f"(d[0]), "+f"(d[1]), "+f"(d[2]), "+f"(d[3])
        : "r"(a[0]), "r"(a[1]), "r"(a[2]), "r"(a[3]), "r"(b[0]), "r"(b[1]));
}
#define CP16(saddr, gptr) \
    asm volatile("cp.async.cg.shared.global [%0], [%1], 16;" :: "r"(saddr), "l"(gptr))
#define CP_COMMIT() asm volatile("cp.async.commit_group;" ::: "memory")
#define CP_WAIT0()  asm volatile("cp.async.wait_group 0;" ::: "memory")

// ---------------- fused prepass: half_logits + normalize + qlab ----------------
__global__ __launch_bounds__(256) void prepass(
    const float* __restrict__ new_logits, const float* __restrict__ new_embeds,
    const int* __restrict__ ql, const int* __restrict__ labels,
    const int* __restrict__ hdrp)
{
    const int b = blockIdx.x, tid = threadIdx.x;
    if (b < 1024) {
        int idx = (b * 256 + tid) * 4;
        float4 v = *(const float4*)(new_logits + idx);
        __half2 h0 = __floats2half2_rn(v.x, v.y);
        __half2 h1 = __floats2half2_rn(v.z, v.w);
        uint2 p; p.x = *(uint32_t*)&h0; p.y = *(uint32_t*)&h1;
        *(uint2*)(g_a2 + idx) = p;
    } else if (b < 1152) {
        int i = b - 1024;
        const float* xr = new_embeds + (size_t)i * DDIM;
        float s = 0.f;
        for (int d = tid; d < DDIM; d += 256) { float v = xr[d]; s += v * v; }
        for (int o = 16; o; o >>= 1) s += __shfl_down_sync(0xffffffffu, s, o);
        __shared__ float sh[8];
        if ((tid & 31) == 0) sh[tid >> 5] = s;
        __syncthreads();
        __shared__ float invs;
        if (tid == 0) {
            float tot = 0.f;
            for (int w = 0; w < 8; w++) tot += sh[w];
            invs = 1.0f / fmaxf(sqrtf(tot), 1e-12f);
        }
        __syncthreads();
        float iv = invs;
        for (int d = tid; d < DDIM; d += 256)
            g_a1[i * DDIM + d] = __half_as_ushort(__float2half_rn(xr[d] * iv));
    } else {
        int j = (b - 1152) * 256 + tid;
        int hdr = *hdrp;
        int r = (j - hdr) & (NQ - 1);
        g_qlab[j] = (r < NROW) ? labels[r] : ql[j];
    }
}

// ---------------- fused fp16 GEMMs + in-epilogue LSE/masked reduction ----------------
// blocks [0,256):   l2 (K=CDIM) -> g_pp[1]
// blocks [256,512): l1 (K=DDIM) -> g_pp[0]
// CTA tile 128x128, BK=32; 8 warps (4M x 2N), warp tile 32x64.
constexpr int BPAD = 80;                 // fp16 tile row stride (conflict-free ldmatrix)
constexpr int FSTR = 144;                // fp32 staging row stride
constexpr int SZ_T = 128 * BPAD;         // 10240
constexpr int SZ_F = 128 * FSTR;         // 18432
constexpr int O_A   = 0;                 // [2 stages x 10240]
constexpr int O_B16 = 2 * SZ_T;          // 20480 [2 stages x 10240]
constexpr int O_FS  = 4 * SZ_T;          // 40960 [2 stages x 18432]
constexpr int GEMM_SMEM = O_FS + 2 * SZ_F;   // 77824 -> 2 CTAs/SM

__global__ __launch_bounds__(256, 2) void gemm_mma(
    const float* __restrict__ Bq2, const float* __restrict__ Bold2,
    const float* __restrict__ Bq1, const float* __restrict__ Bold1,  // = feat_queue, old_embeds
    const int* __restrict__ labels,
    const int* __restrict__ hdrp)
{
    extern __shared__ char smem[];
    const uint32_t sb = smem_u32(smem);
    const int tid = threadIdx.x, lane = tid & 31, wid = tid >> 5;
    const int wm = wid >> 1, wn = wid & 1;
    const int bidx = blockIdx.x;

    // select problem (l2 long blocks first)
    const bool is2 = (bidx < 256);
    const int ctaN = is2 ? bidx : bidx - 256;
    const int n0 = ctaN * 128;
    const int K  = is2 ? CDIM : DDIM;
    const unsigned short* A = is2 ? g_a2 : g_a1;
    const float* Bq   = is2 ? Bq2 : Bq1;
    const float* Bold = is2 ? Bold2 : Bold1;
    const int prob = is2 ? 1 : 0;
    const int nch = K >> 5;

    // B gmem row with circular-queue redirect; 2 threads per row, 64B (16 fp32) each
    const int rb = tid >> 1, seg = tid & 1;
    const int hdr = *hdrp;
    const int j = n0 + rb;
    const int r = (j - hdr) & (NQ - 1);
    const char* gB = (const char*)(((r < NROW) ? (Bold + (size_t)r * K)
                                               : (Bq + (size_t)j * K)) + seg * 16);

    // A: 2 threads per row, 32B each
    const int arow = tid >> 1;
    const int acol = (tid & 1) * 32;
    const char* gA = (const char*)A + (size_t)arow * K * 2 + acol;
    const uint32_t sA = sb + O_A + arow * BPAD + acol;

    // ldmatrix lane addressing
    const int g = lane >> 3, lr = lane & 7;
    const uint32_t aRowOff = (uint32_t)(wm * 32 + (g & 1) * 8 + lr) * BPAD + (g >> 1) * 16;
    const uint32_t bRowOff = (uint32_t)(wn * 64 + (g >> 1) * 8 + lr) * BPAD + (g & 1) * 16;

    float acc[2][8][4];
#pragma unroll
    for (int mt = 0; mt < 2; mt++)
#pragma unroll
        for (int nt = 0; nt < 8; nt++)
#pragma unroll
            for (int u = 0; u < 4; u++) acc[mt][nt][u] = 0.f;

    auto cpA = [&](int c, int st) {
        const char* s0 = gA + (size_t)c * 64;
        uint32_t d0 = sA + st * SZ_T;
        CP16(d0, s0); CP16(d0 + 16, s0 + 16);
    };
    auto cpB = [&](int c, int st) {
        const char* s0 = gB + (size_t)c * 128;
        uint32_t d0 = sb + O_FS + st * SZ_F + rb * FSTR + seg * 64;
#pragma unroll
        for (int i = 0; i < 4; i++) CP16(d0 + 16 * i, s0 + 16 * i);
    };
    auto convertB = [&](int st2) {
        const char* src = smem + O_FS + st2 * SZ_F + rb * FSTR + seg * 64;
        float4 f0 = *(const float4*)(src);
        float4 f1 = *(const float4*)(src + 16);
        float4 f2 = *(const float4*)(src + 32);
        float4 f3 = *(const float4*)(src + 48);
        __half2 h0 = __floats2half2_rn(f0.x, f0.y);
        __half2 h1 = __floats2half2_rn(f0.z, f0.w);
        __half2 h2 = __floats2half2_rn(f1.x, f1.y);
        __half2 h3 = __floats2half2_rn(f1.z, f1.w);
        __half2 h4 = __floats2half2_rn(f2.x, f2.y);
        __half2 h5 = __floats2half2_rn(f2.z, f2.w);
        __half2 h6 = __floats2half2_rn(f3.x, f3.y);
        __half2 h7 = __floats2half2_rn(f3.z, f3.w);
        uint4 p0, p1;
        p0.x = *(uint32_t*)&h0; p0.y = *(uint32_t*)&h1;
        p0.z = *(uint32_t*)&h2; p0.w = *(uint32_t*)&h3;
        p1.x = *(uint32_t*)&h4; p1.y = *(uint32_t*)&h5;
        p1.z = *(uint32_t*)&h6; p1.w = *(uint32_t*)&h7;
        char* d = smem + O_B16 + st2 * SZ_T + rb * BPAD + seg * 32;
        *(uint4*)d = p0;
        *(uint4*)(d + 16) = p1;
    };
    auto computeConv = [&](int c, bool conv) {
        const int st = c & 1;
        const uint32_t bA = sb + O_A + st * SZ_T + aRowOff;
        const uint32_t bB = sb + O_B16 + st * SZ_T + bRowOff;
        {   // ks = 0
            uint32_t a[2][4], b[4][4];
            ldm4(a[0], bA);
            ldm4(a[1], bA + 16 * BPAD);
#pragma unroll
            for (int p = 0; p < 4; p++) ldm4(b[p], bB + p * 16 * BPAD);
#pragma unroll
            for (int mt = 0; mt < 2; mt++)
#pragma unroll
                for (int nt = 0; nt < 8; nt++)
                    mma_f16(acc[mt][nt], a[mt], &b[nt >> 1][(nt & 1) * 2]);
        }
        if (conv) convertB(st ^ 1);
        {   // ks = 1
            uint32_t a[2][4], b[4][4];
            ldm4(a[0], bA + 32);
            ldm4(a[1], bA + 16 * BPAD + 32);
#pragma unroll
            for (int p = 0; p < 4; p++) ldm4(b[p], bB + p * 16 * BPAD + 32);
#pragma unroll
            for (int mt = 0; mt < 2; mt++)
#pragma unroll
                for (int nt = 0; nt < 8; nt++)
                    mma_f16(acc[mt][nt], a[mt], &b[nt >> 1][(nt & 1) * 2]);
        }
    };

    // ---- prologue ----
    cpB(0, 0);
    cpB(1, 1);
    cpA(0, 0);
    CP_COMMIT();
    CP_WAIT0();
    __syncthreads();
    convertB(0);
    __syncthreads();

    // ---- main loop ----
    for (int c = 0; c < nch; c++) {
        const int st = c & 1;
        if (c > 0) { CP_WAIT0(); __syncthreads(); }
        if (c + 2 < nch) cpB(c + 2, st);
        if (c + 1 < nch) cpA(c + 1, st ^ 1);
        CP_COMMIT();
        computeConv(c, c + 1 < nch);
    }

    // ================= fused epilogue: per-row LSE + masked sums =================
    __syncthreads();                       // all compute done; smem reusable
    float* sred = (float*)smem;            // [128 rows][2 wn][8]

    const int qr = lane >> 2, qc = (lane & 3) * 2;
    // own columns (same for all 4 row-sets)
    int ql[16];
#pragma unroll
    for (int nt = 0; nt < 8; nt++) {
        const int col = n0 + wn * 64 + nt * 8 + qc;
        ql[2 * nt]     = g_qlab[col];
        ql[2 * nt + 1] = g_qlab[col + 1];
    }

#pragma unroll
    for (int mt = 0; mt < 2; mt++) {
#pragma unroll
        for (int h = 0; h < 2; h++) {
            const int row = wm * 32 + mt * 16 + h * 8 + qr;
            const int lbl = labels[row];
            float v[16];
#pragma unroll
            for (int nt = 0; nt < 8; nt++) {
                v[2 * nt]     = acc[mt][nt][2 * h];
                v[2 * nt + 1] = acc[mt][nt][2 * h + 1];
            }
            // quad max
            float m = v[0];
#pragma unroll
            for (int e = 1; e < 16; e++) m = fmaxf(m, v[e]);
            m = fmaxf(m, __shfl_xor_sync(0xffffffffu, m, 1));
            m = fmaxf(m, __shfl_xor_sync(0xffffffffu, m, 2));
            // sum exp + masked sums
            float l = 0.f, sw = 0.f, s1 = 0.f, cn = 0.f;
#pragma unroll
            for (int e = 0; e < 16; e++) l += __expf(v[e] - m);
#pragma unroll
            for (int e = 0; e < 16; e++) {
                if (ql[e] == lbl) {
                    const int col = n0 + wn * 64 + (e >> 1) * 8 + qc + (e & 1);
                    const int rr2 = (col - hdr) & (NQ - 1);
                    const float* frow = (rr2 < NROW) ? (Bold1 + (size_t)rr2 * DDIM)
                                                     : (Bq1 + (size_t)col * DDIM);
                    const float* oei = Bold1 + (size_t)row * DDIM;
                    float dot = 0.f;
#pragma unroll 8
                    for (int d = 0; d < DDIM; d++) dot = fmaf(oei[d], frow[d], dot);
                    float w = 0.5f * (dot + 1.0f);
                    sw += w; s1 += w * v[e]; cn += 1.f;
                }
            }
            l  += __shfl_xor_sync(0xffffffffu, l, 1);
            l  += __shfl_xor_sync(0xffffffffu, l, 2);
            sw += __shfl_xor_sync(0xffffffffu, sw, 1);
            sw += __shfl_xor_sync(0xffffffffu, sw, 2);
            s1 += __shfl_xor_sync(0xffffffffu, s1, 1);
            s1 += __shfl_xor_sync(0xffffffffu, s1, 2);
            cn += __shfl_xor_sync(0xffffffffu, cn, 1);
            cn += __shfl_xor_sync(0xffffffffu, cn, 2);
            if ((lane & 3) == 0) {
                float* p = sred + (row * 2 + wn) * 8;
                p[0] = m; p[1] = l; p[2] = sw; p[3] = s1; p[4] = cn;
            }
        }
    }
    __syncthreads();
    if (tid < 128) {
        const float* p0 = sred + (tid * 2 + 0) * 8;
        const float* p1 = sred + (tid * 2 + 1) * 8;
        float M = fmaxf(p0[0], p1[0]);
        float L = p0[1] * __expf(p0[0] - M) + p1[1] * __expf(p1[0] - M);
        float4 a; a.x = M; a.y = L; a.z = p0[2] + p1[2]; a.w = p0[3] + p1[3];
        float4 b; b.x = p0[4] + p1[4]; b.y = 0.f; b.z = 0.f; b.w = 0.f;
        *(float4*)&g_pp[prob][ctaN][tid][0] = a;
        *(float4*)&g_pp[prob][ctaN][tid][4] = b;
    }
}

// ---------------- merge: 256 partials per (prob,row) -> g_terms ----------------
__global__ __launch_bounds__(256) void merge_partials() {
    const int prob = blockIdx.x >> 7, row = blockIdx.x & 127, tid = threadIdx.x;
    float4 a = *(const float4*)&g_pp[prob][tid][row][0];
    float4 b = *(const float4*)&g_pp[prob][tid][row][4];
    float m = a.x, l = a.y, sw = a.z, s1 = a.w, cn = b.x;
    for (int o = 16; o; o >>= 1) {
        float mo = __shfl_down_sync(0xffffffffu, m, o);
        float lo = __shfl_down_sync(0xffffffffu, l, o);
        float nm = fmaxf(m, mo);
        l = l * __expf(m - nm) + lo * __expf(mo - nm);
        m = nm;
        sw += __shfl_down_sync(0xffffffffu, sw, o);
        s1 += __shfl_down_sync(0xffffffffu, s1, o);
        cn += __shfl_down_sync(0xffffffffu, cn, o);
    }
    __shared__ float shm[8], shl[8], shsw[8], shs1[8], shcn[8];
    if ((tid & 31) == 0) {
        int w = tid >> 5;
        shm[w] = m; shl[w] = l; shsw[w] = sw; shs1[w] = s1; shcn[w] = cn;
    }
    __syncthreads();
    if (tid == 0) {
        float M = shm[0], L = shl[0], SW = shsw[0], S1 = shs1[0], CN = shcn[0];
        for (int w = 1; w < 8; w++) {
            float nm = fmaxf(M, shm[w]);
            L = L * __expf(M - nm) + shl[w] * __expf(shm[w] - nm);
            M = nm;
            SW += shsw[w]; S1 += shs1[w]; CN += shcn[w];
        }
        float lse = M + logf(L);
        g_terms[prob * NROW + row] = (S1 - lse * SW) / CN;
    }
}

// ---------------- finalize ----------------
__global__ void finalize(float* __restrict__ out) {
    int tid = threadIdx.x;   // 128 threads, one row each
    float t1 = g_terms[tid];          // prob 0 = l1
    float t2 = g_terms[NROW + tid];   // prob 1 = l2
    for (int o = 16; o; o >>= 1) {
        t1 += __shfl_down_sync(0xffffffffu, t1, o);
        t2 += __shfl_down_sync(0xffffffffu, t2, o);
    }
    __shared__ float sh1[4], sh2[4];
    if ((tid & 31) == 0) { sh1[tid >> 5] = t1; sh2[tid >> 5] = t2; }
    __syncthreads();
    if (tid == 0) {
        out[0] = -(sh1[0] + sh1[1] + sh1[2] + sh1[3]) / (float)NROW;
        out[1] = -(sh2[0] + sh2[1] + sh2[2] + sh2[3]) / (float)NROW;
    }
}

// ---------------- launch ----------------
extern "C" void kernel_launch(void* const* d_in, const int* in_sizes, int n_in,
                              void* d_out, int out_size) {
    const float* old_embeds   = (const float*)d_in[0];
    const float* old_logits   = (const float*)d_in[1];
    const float* new_embeds   = (const float*)d_in[2];
    const float* new_logits   = (const float*)d_in[3];
    const int*   labels       = (const int*)d_in[4];
    const float* feat_queue   = (const float*)d_in[5];
    const float* logit_queue  = (const float*)d_in[6];
    const int*   queue_labels = (const int*)d_in[7];
    const int*   header       = (const int*)d_in[8];
    float* out = (float*)d_out;

    cudaFuncSetAttribute(gemm_mma, cudaFuncAttributeMaxDynamicSharedMemorySize, GEMM_SMEM);

    prepass<<<1280, 256>>>(new_logits, new_embeds, queue_labels, labels, header);

    // fused: [0,256) l2 (K=CDIM) -> g_pp[1], [256,512) l1 (K=DDIM) -> g_pp[0]
    gemm_mma<<<512, 256, GEMM_SMEM>>>(logit_queue, old_logits,
                                      feat_queue, old_embeds, labels, header);

    merge_partials<<<2 * NROW, 256>>>();
    finalize<<<1, 128>>>(out);
}